// round 14
// baseline (speedup 1.0000x reference)
#include <cuda_runtime.h>
#include <cstdint>

#define B_    16
#define T_    2048
#define D_    1024
#define TT_   2046
#define MW_   682
#define M_    (B_ * MW_)          // 10912
#define MPAD  11008               // 86 * 128 = 172 * 64
#define NMUT  64
#define NBIN  32
#define NHEAD 96                  // 64 class + 32 binary (fused)
#define KSPLIT 4

// All GEMM operand tensors stored with each 8-wide k-group permuted:
// logical k -> storage position p(k) = 2*(k&3) | (k>>2)  (LDS.64 frag pairs).
__device__ float g_wf[MPAD * D_];        // word features, tf32, k-permuted
__device__ float g_h [MPAD * D_];        // tanh hidden, tf32, k-permuted
__device__ float g_wt[D_ * D_];          // dense_w, tf32, k-permuted
__device__ float g_hw[NHEAD * D_];       // fused head weights, tf32, k-permuted
__device__ float g_hb[NHEAD];            // fused head bias
__device__ float g_part[KSPLIT * MPAD * NHEAD];  // head split-K partials
__device__ int   g_begin[M_];
__device__ int   g_cnt  [M_];

// ===========================================================================
// helpers
// ===========================================================================
__device__ __forceinline__ uint32_t smem_u32(const void* p) {
    return (uint32_t)__cvta_generic_to_shared(p);
}
__device__ __forceinline__ void cp16(uint32_t dst, const void* src) {
    asm volatile("cp.async.cg.shared.global [%0], [%1], 16;\n" :: "r"(dst), "l"(src));
}
#define CP_COMMIT() asm volatile("cp.async.commit_group;" ::: "memory")

__device__ __forceinline__ float f2tf(float x) {
    uint32_t r;
    asm("cvt.rna.tf32.f32 %0, %1;" : "=r"(r) : "f"(x));
    return __uint_as_float(r);
}
__device__ __forceinline__ float tanh_fast(float x) {
    float y;
    asm("tanh.approx.f32 %0, %1;" : "=f"(y) : "f"(x));
    return y;
}
__device__ __forceinline__ int kperm8(int l) {       // l in 0..7
    return ((l & 3) << 1) | (l >> 2);
}
__device__ __forceinline__ void mma8(float* c, const uint32_t* a, const uint32_t* b) {
    asm volatile("mma.sync.aligned.m16n8k8.row.col.f32.tf32.tf32.f32 "
        "{%0,%1,%2,%3}, {%4,%5,%6,%7}, {%8,%9}, {%0,%1,%2,%3};"
        : "+f"(c[0]), "+f"(c[1]), "+f"(c[2]), "+f"(c[3])
        : "r"(a[0]), "r"(a[1]), "r"(a[2]), "r"(a[3]), "r"(b[0]), "r"(b[1]));
}

// ===========================================================================
// 1) per-batch scan of word_starts -> word begin token + token count
// ===========================================================================
__global__ void scan_kernel(const int* __restrict__ ws) {
    int b = blockIdx.x;
    const int* w = ws + b * TT_;
    __shared__ int partial[256];
    __shared__ int scnt[MW_];
    int tid = threadIdx.x;
    for (int i = tid; i < MW_; i += 256) scnt[i] = 0;

    int vals[8];
    int s = 0;
#pragma unroll
    for (int i = 0; i < 8; i++) {
        int t = tid * 8 + i;
        int v = (t < TT_) ? w[t] : 0;
        vals[i] = v; s += v;
    }
    partial[tid] = s;
    __syncthreads();
    for (int off = 1; off < 256; off <<= 1) {
        int v = partial[tid];
        int add = (tid >= off) ? partial[tid - off] : 0;
        __syncthreads();
        partial[tid] = v + add;
        __syncthreads();
    }
    int run = (tid > 0) ? partial[tid - 1] : 0;
#pragma unroll
    for (int i = 0; i < 8; i++) {
        int t = tid * 8 + i;
        if (t < TT_) {
            run += vals[i];
            int seg = run - 1;
            if (seg >= 0 && seg < MW_) {
                if (vals[i]) g_begin[b * MW_ + seg] = t;
                atomicAdd(&scnt[seg], 1);
            }
        }
    }
    __syncthreads();
    for (int i = tid; i < MW_; i += 256) g_cnt[b * MW_ + i] = scnt[i];
}

// ===========================================================================
// 2) word-feature segment sums, tf32-rounded, k-permuted store
// ===========================================================================
__global__ void wf_kernel(const float* __restrict__ feat) {
    int m = blockIdx.x;
    int b = m / MW_;
    int tid = threadIdx.x;                       // float4 index 0..255
    int cnt = g_cnt[m];
    float* orow = g_wf + (size_t)m * D_;
    int base8 = (4 * tid) & ~7;
    int o = tid & 1;
    float* dst = orow + base8 + o;
    if (cnt == 0) {
        float one = f2tf(1.f);
        dst[0] = one; dst[2] = one; dst[4] = one; dst[6] = one;
        return;
    }
    int t0 = g_begin[m];
    const float4* base = (const float4*)(feat + ((size_t)b * T_ + 1 + t0) * D_);
    float4 acc = base[tid];
    for (int i = 1; i < cnt; i++) {
        float4 v = base[(size_t)i * (D_ / 4) + tid];
        acc.x += v.x; acc.y += v.y; acc.z += v.z; acc.w += v.w;
    }
    dst[0] = f2tf(acc.x); dst[2] = f2tf(acc.y);
    dst[4] = f2tf(acc.z); dst[6] = f2tf(acc.w);
}

// ===========================================================================
// 2b) tf32 round-copy of dense_w, k-permuted (needed before tc_main)
// ===========================================================================
__global__ void roundw_kernel(const float* __restrict__ src) {
    int i = blockIdx.x * 256 + threadIdx.x;      // float4 index
    float4 v = ((const float4*)src)[i];
    int base8 = (4 * i) & ~7;
    int o = i & 1;
    float* dst = g_wt + base8 + o;
    dst[0] = f2tf(v.x); dst[2] = f2tf(v.y); dst[4] = f2tf(v.z); dst[6] = f2tf(v.w);
}

// ===========================================================================
// 3a) g_hw rows 0..63 = round(out_w) k-permuted; g_hb[0..63] = out_b
//     (side stream, only needed by tc_head)
// ===========================================================================
__global__ void headw_copy(const float* __restrict__ out_w, const float* __restrict__ out_b) {
    int i = blockIdx.x * 256 + threadIdx.x;      // float4 index over 64*1024
    float4 v = ((const float4*)out_w)[i];
    int base8 = (4 * i) & ~7;
    int o = i & 1;
    float* dst = g_hw + base8 + o;
    dst[0] = f2tf(v.x); dst[2] = f2tf(v.y); dst[4] = f2tf(v.z); dst[6] = f2tf(v.w);
    if (blockIdx.x == 0 && threadIdx.x < NMUT) g_hb[threadIdx.x] = out_b[threadIdx.x];
}

// ===========================================================================
// 3b) g_hw rows 64..95 = round(bin_w[:,64:] + bin_w[:,:64] @ out_w), k-permuted
//     grid (16 col-slices x 4 row-groups), 64 cols/block (side stream)
// ===========================================================================
__global__ void headw_bin(const float* __restrict__ out_w, const float* __restrict__ out_b,
                          const float* __restrict__ bin_w, const float* __restrict__ bin_b) {
    __shared__ float w1[8][NMUT];
    int tid = threadIdx.x;
    int col0 = blockIdx.x * 64;
    int rb   = blockIdx.y * 8;                   // rows rb..rb+7 of the 32
    for (int i = tid; i < 8 * NMUT; i += 256) {
        int r = i >> 6, j = i & 63;
        w1[r][j] = bin_w[(size_t)(rb + r) * (D_ + NMUT) + j];
    }
    __syncthreads();

    int col = col0 + (tid & 63);
    int rh  = (tid >> 6) * 2;                    // local rows rh, rh+1
    float acc0 = bin_w[(size_t)(rb + rh + 0) * (D_ + NMUT) + NMUT + col];
    float acc1 = bin_w[(size_t)(rb + rh + 1) * (D_ + NMUT) + NMUT + col];
#pragma unroll 8
    for (int j = 0; j < NMUT; j++) {
        float v = __ldg(out_w + (size_t)j * D_ + col);
        acc0 += w1[rh + 0][j] * v;
        acc1 += w1[rh + 1][j] * v;
    }
    int pc = (col & ~7) | kperm8(col & 7);
    g_hw[(size_t)(NMUT + rb + rh + 0) * D_ + pc] = f2tf(acc0);
    g_hw[(size_t)(NMUT + rb + rh + 1) * D_ + pc] = f2tf(acc1);

    if (blockIdx.x == 0 && blockIdx.y == 0 && tid < NBIN) {
        float bb = bin_b[tid];
        for (int j = 0; j < NMUT; j++)
            bb += bin_w[(size_t)tid * (D_ + NMUT) + j] * out_b[j];
        g_hb[NMUT + tid] = bb;
    }
}

// ===========================================================================
// 4) main tf32 GEMM: h = tanh(wf @ wt^T + b), 128x128 tile, BK=32, 2-stage,
//    512 threads, 16 warps (4m x 4n), warp tile 32x32, <=64 regs -> 2 CTA/SM
//    (32 warps/SM: doubles latency hiding vs the 256-thread/128-reg shape)
// ===========================================================================
__global__ __launch_bounds__(512, 2) void tc_main(
    const float* __restrict__ A, const float* __restrict__ Bw,
    const float* __restrict__ bias, float* __restrict__ O1)
{
    constexpr int AST = 128 * 40;
    constexpr int BST = 128 * 40;
    extern __shared__ float smem[];
    float* Asm = smem;                           // [2][128][40]
    float* Bsm = smem + 2 * AST;                 // [2][128][40]

    const int tid = threadIdx.x;
    const int lane = tid & 31, wid = tid >> 5;   // 16 warps
    const int g = lane >> 2, tg = lane & 3;
    const int wm = (wid & 3) * 32;
    const int wn = (wid >> 2) * 32;
    const int row0 = blockIdx.y * 128;
    const int col0 = blockIdx.x * 128;

    float acc[2][4][4];
#pragma unroll
    for (int i = 0; i < 2; i++)
#pragma unroll
        for (int j = 0; j < 4; j++)
#pragma unroll
            for (int q = 0; q < 4; q++) acc[i][j][q] = 0.f;

    const float* Ab = A + (size_t)row0 * D_;
    const float* Bb = Bw + (size_t)col0 * D_;

    auto loadStage = [&](int st, int k0) {
        float* Ad = Asm + st * AST;
#pragma unroll
        for (int i = tid; i < 1024; i += 512) {
            int r = i >> 3, c = i & 7;
            cp16(smem_u32(Ad + r * 40 + c * 4), Ab + (size_t)r * D_ + k0 + c * 4);
        }
        float* Bd = Bsm + st * BST;
#pragma unroll
        for (int i = tid; i < 1024; i += 512) {
            int r = i >> 3, c = i & 7;
            cp16(smem_u32(Bd + r * 40 + c * 4), Bb + (size_t)r * D_ + k0 + c * 4);
        }
        CP_COMMIT();
    };
    auto compute = [&](int st) {
        const float* Ad = Asm + st * AST;
        const float* Bd = Bsm + st * BST;
#pragma unroll
        for (int ks = 0; ks < 4; ks++) {
            const int kk = ks * 8 + 2 * tg;
            uint32_t a[2][4];
#pragma unroll
            for (int i = 0; i < 2; i++) {
                const float* ap = Ad + (wm + i * 16 + g) * 40 + kk;
                uint2 v0 = *(const uint2*)ap;            // k=tg, k=tg+4
                uint2 v1 = *(const uint2*)(ap + 8 * 40);
                a[i][0] = v0.x; a[i][2] = v0.y;
                a[i][1] = v1.x; a[i][3] = v1.y;
            }
#pragma unroll
            for (int j = 0; j < 4; j++) {
                const float* bp = Bd + (wn + j * 8 + g) * 40 + kk;
                uint2 vb = *(const uint2*)bp;
                uint32_t b[2] = { vb.x, vb.y };
                mma8(acc[0][j], a[0], b);
                mma8(acc[1][j], a[1], b);
            }
        }
    };

    loadStage(0, 0);
    int st = 0;
    for (int k0 = 0; k0 < D_; k0 += 32) {
        asm volatile("cp.async.wait_group 0;" ::: "memory");
        __syncthreads();
        if (k0 + 32 < D_) loadStage(st ^ 1, k0 + 32);
        compute(st);
        st ^= 1;
    }

    // epilogue: bias + tanh.approx, tf32-round, k-permuted scalar stores
#pragma unroll
    for (int i = 0; i < 2; i++) {
#pragma unroll
        for (int j = 0; j < 4; j++) {
            int r = row0 + wm + i * 16 + g;
            int c = col0 + wn + j * 8 + tg * 2;
            int cb = c & ~7;
            int p0 = cb + kperm8(c & 7);
            int p1 = cb + kperm8((c + 1) & 7);
            float x0 = f2tf(tanh_fast(acc[i][j][0] + bias[c]));
            float x1 = f2tf(tanh_fast(acc[i][j][1] + bias[c + 1]));
            float x2 = f2tf(tanh_fast(acc[i][j][2] + bias[c]));
            float x3 = f2tf(tanh_fast(acc[i][j][3] + bias[c + 1]));
            O1[(size_t)r * D_ + p0] = x0;
            O1[(size_t)r * D_ + p1] = x1;
            O1[(size_t)(r + 8) * D_ + p0] = x2;
            O1[(size_t)(r + 8) * D_ + p1] = x3;
        }
    }
}

// ===========================================================================
// 5) head GEMM split-K: partial[s][64-row tile][96] = h @ g_hw^T over k-slice s
//    grid (172, 4); each CTA: BM=64, BN=96, K=256 (8 x BK=32 iterations).
// ===========================================================================
__global__ __launch_bounds__(256) void tc_head(
    const float* __restrict__ A, const float* __restrict__ Bw)
{
    constexpr int AST = 64 * 40;
    constexpr int BST = 96 * 40;
    extern __shared__ float smem[];
    float* Asm = smem;                           // [2][64][40]
    float* Bsm = smem + 2 * AST;                 // [2][96][40]

    const int tid = threadIdx.x;
    const int lane = tid & 31, wid = tid >> 5;
    const int g = lane >> 2, tg = lane & 3;
    const int wm = (wid & 1) * 32;
    const int wn = (wid >> 1) * 24;
    const int row0 = blockIdx.x * 64;
    const int kbase = blockIdx.y * (D_ / KSPLIT);   // 256-wide k slice

    float acc[2][3][4];
#pragma unroll
    for (int i = 0; i < 2; i++)
#pragma unroll
        for (int j = 0; j < 3; j++)
#pragma unroll
            for (int q = 0; q < 4; q++) acc[i][j][q] = 0.f;

    const float* Ab = A + (size_t)row0 * D_;

    auto loadStage = [&](int st, int k0) {
        float* Ad = Asm + st * AST;
#pragma unroll
        for (int i = tid; i < 512; i += 256) {
            int r = i >> 3, c = i & 7;
            cp16(smem_u32(Ad + r * 40 + c * 4), Ab + (size_t)r * D_ + k0 + c * 4);
        }
        float* Bd = Bsm + st * BST;
#pragma unroll
        for (int i = tid; i < 768; i += 256) {
            int r = i >> 3, c = i & 7;
            cp16(smem_u32(Bd + r * 40 + c * 4), Bw + (size_t)r * D_ + k0 + c * 4);
        }
        CP_COMMIT();
    };
    auto compute = [&](int st) {
        const float* Ad = Asm + st * AST;
        const float* Bd = Bsm + st * BST;
#pragma unroll
        for (int ks = 0; ks < 4; ks++) {
            const int kk = ks * 8 + 2 * tg;
            uint32_t a[2][4];
#pragma unroll
            for (int i = 0; i < 2; i++) {
                const float* ap = Ad + (wm + i * 16 + g) * 40 + kk;
                uint2 v0 = *(const uint2*)ap;
                uint2 v1 = *(const uint2*)(ap + 8 * 40);
                a[i][0] = v0.x; a[i][2] = v0.y;
                a[i][1] = v1.x; a[i][3] = v1.y;
            }
#pragma unroll
            for (int j = 0; j < 3; j++) {
                const float* bp = Bd + (wn + j * 8 + g) * 40 + kk;
                uint2 vb = *(const uint2*)bp;
                uint32_t b[2] = { vb.x, vb.y };
                mma8(acc[0][j], a[0], b);
                mma8(acc[1][j], a[1], b);
            }
        }
    };

    loadStage(0, kbase);
    int st = 0;
    for (int kk = 0; kk < D_ / KSPLIT; kk += 32) {
        asm volatile("cp.async.wait_group 0;" ::: "memory");
        __syncthreads();
        if (kk + 32 < D_ / KSPLIT) loadStage(st ^ 1, kbase + kk + 32);
        compute(st);
        st ^= 1;
    }

    float* P = g_part + (size_t)blockIdx.y * MPAD * NHEAD;
#pragma unroll
    for (int i = 0; i < 2; i++) {
#pragma unroll
        for (int j = 0; j < 3; j++) {
            int c = wn + j * 8 + tg * 2;
#pragma unroll
            for (int rr = 0; rr < 2; rr++) {
                int row = row0 + wm + i * 16 + g + rr * 8;
                float2 v;
                v.x = acc[i][j][rr * 2 + 0];
                v.y = acc[i][j][rr * 2 + 1];
                *(float2*)(P + (size_t)row * NHEAD + c) = v;
            }
        }
    }
}

// ===========================================================================
// 6) reduce split-K partials + bias -> wcl / bin (float4 path)
// ===========================================================================
__global__ void reduce_head(float* __restrict__ wcl, float* __restrict__ bin) {
    int i = blockIdx.x * 256 + threadIdx.x;      // 4-col group index
    if (i >= M_ * (NHEAD / 4)) return;
    int r = i / (NHEAD / 4), cg = i - r * (NHEAD / 4);
    int c = cg * 4;
    float4 s = *(const float4*)(g_hb + c);
#pragma unroll
    for (int p = 0; p < KSPLIT; p++) {
        float4 v = *(const float4*)(g_part + (size_t)p * MPAD * NHEAD + (size_t)r * NHEAD + c);
        s.x += v.x; s.y += v.y; s.z += v.z; s.w += v.w;
    }
    if (c < NMUT) *(float4*)(wcl + (size_t)r * NMUT + c) = s;
    else          *(float4*)(bin + (size_t)r * NBIN + (c - NMUT)) = s;
}

// ===========================================================================
extern "C" void kernel_launch(void* const* d_in, const int* in_sizes, int n_in,
                              void* d_out, int out_size)
{
    const float* features = (const float*)d_in[0];
    const int*   wstarts  = (const int*)d_in[1];
    const float* dense_w  = (const float*)d_in[2];
    const float* dense_b  = (const float*)d_in[3];
    const float* out_w    = (const float*)d_in[4];
    const float* out_b    = (const float*)d_in[5];
    const float* bin_w    = (const float*)d_in[6];
    const float* bin_b    = (const float*)d_in[7];
    (void)in_sizes; (void)n_in; (void)out_size;

    float *wf, *h, *wt, *hw;
    cudaGetSymbolAddress((void**)&wf, g_wf);
    cudaGetSymbolAddress((void**)&h,  g_h);
    cudaGetSymbolAddress((void**)&wt, g_wt);
    cudaGetSymbolAddress((void**)&hw, g_hw);

    float* wcl = (float*)d_out;                        // [M, 64]
    float* bin = (float*)d_out + (size_t)M_ * NMUT;    // [M, 32]

    const int SMEM_MAIN = 2 * (128 * 40 + 128 * 40) * 4;   // 81920
    const int SMEM_HEAD = 2 * (64 * 40 + 96 * 40) * 4;     // 51200
    cudaFuncSetAttribute(tc_main, cudaFuncAttributeMaxDynamicSharedMemorySize, SMEM_MAIN);
    cudaFuncSetAttribute(tc_head, cudaFuncAttributeMaxDynamicSharedMemorySize, SMEM_HEAD);

    // one-time side stream + fork/join events (created outside capture on the
    // first (correctness) call; reused identically on every call thereafter)
    static cudaStream_t s_side = nullptr;
    static cudaEvent_t ev_fork = nullptr, ev_join = nullptr;
    if (s_side == nullptr) {
        cudaStreamCreateWithFlags(&s_side, cudaStreamNonBlocking);
        cudaEventCreateWithFlags(&ev_fork, cudaEventDisableTiming);
        cudaEventCreateWithFlags(&ev_join, cudaEventDisableTiming);
    }

    // ---- main stream: scan(1), wf(2), roundw(3), tc_main(4) ----
    cudaEventRecord(ev_fork, 0);
    scan_kernel<<<B_, 256>>>(wstarts);
    wf_kernel<<<M_, 256>>>(features);
    roundw_kernel<<<D_ * D_ / 4 / 256, 256>>>(dense_w);
    tc_main<<<dim3(8, MPAD / 128), 512, SMEM_MAIN>>>(wf, wt, dense_b, h);

    // ---- side stream (concurrent with the above): head-weight prep ----
    cudaStreamWaitEvent(s_side, ev_fork, 0);
    headw_copy<<<NMUT * D_ / 4 / 256, 256, 0, s_side>>>(out_w, out_b);
    headw_bin<<<dim3(16, 4), 256, 0, s_side>>>(out_w, out_b, bin_w, bin_b);
    cudaEventRecord(ev_join, s_side);

    // ---- join, then heads ----
    cudaStreamWaitEvent(0, ev_join, 0);
    tc_head<<<dim3(MPAD / 64, KSPLIT), 256, SMEM_HEAD>>>(h, hw);
    reduce_head<<<(M_ * (NHEAD / 4) + 255) / 256, 256>>>(wcl, bin);
}

// round 15
// speedup vs baseline: 1.0078x; 1.0078x over previous
#include <cuda_runtime.h>
#include <cstdint>

#define B_    16
#define T_    2048
#define D_    1024
#define TT_   2046
#define MW_   682
#define M_    (B_ * MW_)          // 10912
#define MPAD  11008               // 86 * 128 = 172 * 64
#define NMUT  64
#define NBIN  32
#define NHEAD 96                  // 64 class + 32 binary (fused)
#define KSPLIT 4

// All GEMM operand tensors stored with each 8-wide k-group permuted:
// logical k -> storage position p(k) = 2*(k&3) | (k>>2)  (LDS.64 frag pairs).
__device__ float g_wf[MPAD * D_];        // word features, tf32, k-permuted
__device__ float g_h [MPAD * D_];        // tanh hidden, tf32, k-permuted
__device__ float g_wt[D_ * D_];          // dense_w, tf32, k-permuted
__device__ float g_hw[NHEAD * D_];       // fused head weights, tf32, k-permuted
__device__ float g_hb[NHEAD];            // fused head bias
__device__ float g_part[KSPLIT * MPAD * NHEAD];  // head split-K partials
__device__ int   g_begin[M_];
__device__ int   g_cnt  [M_];

// ===========================================================================
// helpers
// ===========================================================================
__device__ __forceinline__ uint32_t smem_u32(const void* p) {
    return (uint32_t)__cvta_generic_to_shared(p);
}
__device__ __forceinline__ void cp16(uint32_t dst, const void* src) {
    asm volatile("cp.async.cg.shared.global [%0], [%1], 16;\n" :: "r"(dst), "l"(src));
}
#define CP_COMMIT() asm volatile("cp.async.commit_group;" ::: "memory")

__device__ __forceinline__ float f2tf(float x) {
    uint32_t r;
    asm("cvt.rna.tf32.f32 %0, %1;" : "=r"(r) : "f"(x));
    return __uint_as_float(r);
}
__device__ __forceinline__ float tanh_fast(float x) {
    float y;
    asm("tanh.approx.f32 %0, %1;" : "=f"(y) : "f"(x));
    return y;
}
__device__ __forceinline__ int kperm8(int l) {       // l in 0..7
    return ((l & 3) << 1) | (l >> 2);
}
__device__ __forceinline__ void mma8(float* c, const uint32_t* a, const uint32_t* b) {
    asm volatile("mma.sync.aligned.m16n8k8.row.col.f32.tf32.tf32.f32 "
        "{%0,%1,%2,%3}, {%4,%5,%6,%7}, {%8,%9}, {%0,%1,%2,%3};"
        : "+f"(c[0]), "+f"(c[1]), "+f"(c[2]), "+f"(c[3])
        : "r"(a[0]), "r"(a[1]), "r"(a[2]), "r"(a[3]), "r"(b[0]), "r"(b[1]));
}

// ===========================================================================
// 1) per-batch scan of word_starts -> word begin token + token count
// ===========================================================================
__global__ void scan_kernel(const int* __restrict__ ws) {
    int b = blockIdx.x;
    const int* w = ws + b * TT_;
    __shared__ int partial[256];
    __shared__ int scnt[MW_];
    int tid = threadIdx.x;
    for (int i = tid; i < MW_; i += 256) scnt[i] = 0;

    int vals[8];
    int s = 0;
#pragma unroll
    for (int i = 0; i < 8; i++) {
        int t = tid * 8 + i;
        int v = (t < TT_) ? w[t] : 0;
        vals[i] = v; s += v;
    }
    partial[tid] = s;
    __syncthreads();
    for (int off = 1; off < 256; off <<= 1) {
        int v = partial[tid];
        int add = (tid >= off) ? partial[tid - off] : 0;
        __syncthreads();
        partial[tid] = v + add;
        __syncthreads();
    }
    int run = (tid > 0) ? partial[tid - 1] : 0;
#pragma unroll
    for (int i = 0; i < 8; i++) {
        int t = tid * 8 + i;
        if (t < TT_) {
            run += vals[i];
            int seg = run - 1;
            if (seg >= 0 && seg < MW_) {
                if (vals[i]) g_begin[b * MW_ + seg] = t;
                atomicAdd(&scnt[seg], 1);
            }
        }
    }
    __syncthreads();
    for (int i = tid; i < MW_; i += 256) g_cnt[b * MW_ + i] = scnt[i];
}

// ===========================================================================
// 2) word-feature segment sums, tf32-rounded, k-permuted store
// ===========================================================================
__global__ void wf_kernel(const float* __restrict__ feat) {
    int m = blockIdx.x;
    int b = m / MW_;
    int tid = threadIdx.x;                       // float4 index 0..255
    int cnt = g_cnt[m];
    float* orow = g_wf + (size_t)m * D_;
    int base8 = (4 * tid) & ~7;
    int o = tid & 1;
    float* dst = orow + base8 + o;
    if (cnt == 0) {
        float one = f2tf(1.f);
        dst[0] = one; dst[2] = one; dst[4] = one; dst[6] = one;
        return;
    }
    int t0 = g_begin[m];
    const float4* base = (const float4*)(feat + ((size_t)b * T_ + 1 + t0) * D_);
    float4 acc = base[tid];
    for (int i = 1; i < cnt; i++) {
        float4 v = base[(size_t)i * (D_ / 4) + tid];
        acc.x += v.x; acc.y += v.y; acc.z += v.z; acc.w += v.w;
    }
    dst[0] = f2tf(acc.x); dst[2] = f2tf(acc.y);
    dst[4] = f2tf(acc.z); dst[6] = f2tf(acc.w);
}

// ===========================================================================
// 2b) tf32 round-copy of dense_w, k-permuted (side stream; needed by tc_main)
// ===========================================================================
__global__ void roundw_kernel(const float* __restrict__ src) {
    int i = blockIdx.x * 256 + threadIdx.x;      // float4 index
    float4 v = ((const float4*)src)[i];
    int base8 = (4 * i) & ~7;
    int o = i & 1;
    float* dst = g_wt + base8 + o;
    dst[0] = f2tf(v.x); dst[2] = f2tf(v.y); dst[4] = f2tf(v.z); dst[6] = f2tf(v.w);
}

// ===========================================================================
// 3a) g_hw rows 0..63 = round(out_w) k-permuted; g_hb[0..63] = out_b
// ===========================================================================
__global__ void headw_copy(const float* __restrict__ out_w, const float* __restrict__ out_b) {
    int i = blockIdx.x * 256 + threadIdx.x;      // float4 index over 64*1024
    float4 v = ((const float4*)out_w)[i];
    int base8 = (4 * i) & ~7;
    int o = i & 1;
    float* dst = g_hw + base8 + o;
    dst[0] = f2tf(v.x); dst[2] = f2tf(v.y); dst[4] = f2tf(v.z); dst[6] = f2tf(v.w);
    if (blockIdx.x == 0 && threadIdx.x < NMUT) g_hb[threadIdx.x] = out_b[threadIdx.x];
}

// ===========================================================================
// 3b) g_hw rows 64..95 = round(bin_w[:,64:] + bin_w[:,:64] @ out_w), k-permuted
// ===========================================================================
__global__ void headw_bin(const float* __restrict__ out_w, const float* __restrict__ out_b,
                          const float* __restrict__ bin_w, const float* __restrict__ bin_b) {
    __shared__ float w1[8][NMUT];
    int tid = threadIdx.x;
    int col0 = blockIdx.x * 64;
    int rb   = blockIdx.y * 8;                   // rows rb..rb+7 of the 32
    for (int i = tid; i < 8 * NMUT; i += 256) {
        int r = i >> 6, j = i & 63;
        w1[r][j] = bin_w[(size_t)(rb + r) * (D_ + NMUT) + j];
    }
    __syncthreads();

    int col = col0 + (tid & 63);
    int rh  = (tid >> 6) * 2;                    // local rows rh, rh+1
    float acc0 = bin_w[(size_t)(rb + rh + 0) * (D_ + NMUT) + NMUT + col];
    float acc1 = bin_w[(size_t)(rb + rh + 1) * (D_ + NMUT) + NMUT + col];
#pragma unroll 8
    for (int j = 0; j < NMUT; j++) {
        float v = __ldg(out_w + (size_t)j * D_ + col);
        acc0 += w1[rh + 0][j] * v;
        acc1 += w1[rh + 1][j] * v;
    }
    int pc = (col & ~7) | kperm8(col & 7);
    g_hw[(size_t)(NMUT + rb + rh + 0) * D_ + pc] = f2tf(acc0);
    g_hw[(size_t)(NMUT + rb + rh + 1) * D_ + pc] = f2tf(acc1);

    if (blockIdx.x == 0 && blockIdx.y == 0 && tid < NBIN) {
        float bb = bin_b[tid];
        for (int j = 0; j < NMUT; j++)
            bb += bin_w[(size_t)tid * (D_ + NMUT) + j] * out_b[j];
        g_hb[NMUT + tid] = bb;
    }
}

// ===========================================================================
// 4) main tf32 GEMM: h = tanh(wf @ wt^T + b), 128x128 tile, BK=32, 2-stage,
//    256 threads, 8 warps (4m x 2n), warp tile 32x64 (R13 best config),
//    all cp.async addressing hoisted out of the mainloop.
// ===========================================================================
__global__ __launch_bounds__(256) void tc_main(
    const float* __restrict__ A, const float* __restrict__ Bw,
    const float* __restrict__ bias, float* __restrict__ O1)
{
    constexpr int AST = 128 * 40;
    constexpr int BST = 128 * 40;
    extern __shared__ float smem[];
    float* Asm = smem;                           // [2][128][40]
    float* Bsm = smem + 2 * AST;                 // [2][128][40]

    const int tid = threadIdx.x;
    const int lane = tid & 31, wid = tid >> 5;
    const int g = lane >> 2, tg = lane & 3;
    const int wm = (wid & 3) * 32;
    const int wn = (wid >> 2) * 64;
    const int row0 = blockIdx.y * 128;
    const int col0 = blockIdx.x * 128;

    float acc[2][8][4];
#pragma unroll
    for (int i = 0; i < 2; i++)
#pragma unroll
        for (int j = 0; j < 8; j++)
#pragma unroll
            for (int q = 0; q < 4; q++) acc[i][j][q] = 0.f;

    // ---- hoisted cp.async addressing (computed once) ----
    const int lr = tid >> 3;                     // row base 0..31
    const int lc = (tid & 7) * 4;                // float col within 32
    const float* aS = A  + (size_t)(row0 + lr) * D_ + lc;
    const float* bS = Bw + (size_t)(col0 + lr) * D_ + lc;
    uint32_t aD0 = smem_u32(Asm + lr * 40 + lc);
    uint32_t bD0 = smem_u32(Bsm + lr * 40 + lc);
    constexpr uint32_t STG = AST * 4;            // bytes per stage
    constexpr uint32_t RSTEP = 32 * 40 * 4;      // 32 rows of smem
    constexpr size_t   GSTEP = (size_t)32 * D_;  // 32 rows of gmem

    auto loadStage = [&](int st) {
        uint32_t ad = aD0 + (uint32_t)st * STG;
        uint32_t bd = bD0 + (uint32_t)st * STG;
#pragma unroll
        for (int q = 0; q < 4; q++) {
            cp16(ad + q * RSTEP, aS + q * GSTEP);
            cp16(bd + q * RSTEP, bS + q * GSTEP);
        }
        CP_COMMIT();
        aS += 32; bS += 32;                      // next 32-wide k chunk
    };
    auto compute = [&](int st) {
        const float* Ad = Asm + st * AST;
        const float* Bd = Bsm + st * BST;
#pragma unroll
        for (int ks = 0; ks < 4; ks++) {
            const int kk = ks * 8 + 2 * tg;
            uint32_t a[2][4];
#pragma unroll
            for (int i = 0; i < 2; i++) {
                const float* ap = Ad + (wm + i * 16 + g) * 40 + kk;
                uint2 v0 = *(const uint2*)ap;            // k=tg, k=tg+4
                uint2 v1 = *(const uint2*)(ap + 8 * 40);
                a[i][0] = v0.x; a[i][2] = v0.y;
                a[i][1] = v1.x; a[i][3] = v1.y;
            }
#pragma unroll
            for (int j = 0; j < 8; j++) {
                const float* bp = Bd + (wn + j * 8 + g) * 40 + kk;
                uint2 vb = *(const uint2*)bp;
                uint32_t b[2] = { vb.x, vb.y };
                mma8(acc[0][j], a[0], b);
                mma8(acc[1][j], a[1], b);
            }
        }
    };

    loadStage(0);
    int st = 0;
    for (int k0 = 0; k0 < D_; k0 += 32) {
        asm volatile("cp.async.wait_group 0;" ::: "memory");
        __syncthreads();
        if (k0 + 32 < D_) loadStage(st ^ 1);
        compute(st);
        st ^= 1;
    }

    // epilogue: bias + tanh.approx, tf32-round, k-permuted scalar stores
#pragma unroll
    for (int i = 0; i < 2; i++) {
#pragma unroll
        for (int j = 0; j < 8; j++) {
            int r = row0 + wm + i * 16 + g;
            int c = col0 + wn + j * 8 + tg * 2;
            int cb = c & ~7;
            int p0 = cb + kperm8(c & 7);
            int p1 = cb + kperm8((c + 1) & 7);
            float x0 = f2tf(tanh_fast(acc[i][j][0] + bias[c]));
            float x1 = f2tf(tanh_fast(acc[i][j][1] + bias[c + 1]));
            float x2 = f2tf(tanh_fast(acc[i][j][2] + bias[c]));
            float x3 = f2tf(tanh_fast(acc[i][j][3] + bias[c + 1]));
            O1[(size_t)r * D_ + p0] = x0;
            O1[(size_t)r * D_ + p1] = x1;
            O1[(size_t)(r + 8) * D_ + p0] = x2;
            O1[(size_t)(r + 8) * D_ + p1] = x3;
        }
    }
}

// ===========================================================================
// 5) head GEMM split-K: partial[s][64-row tile][96] = h @ g_hw^T over k-slice s
//    grid (172, 4); each CTA: BM=64, BN=96, K=256 (8 x BK=32 iterations).
// ===========================================================================
__global__ __launch_bounds__(256) void tc_head(
    const float* __restrict__ A, const float* __restrict__ Bw)
{
    constexpr int AST = 64 * 40;
    constexpr int BST = 96 * 40;
    extern __shared__ float smem[];
    float* Asm = smem;                           // [2][64][40]
    float* Bsm = smem + 2 * AST;                 // [2][96][40]

    const int tid = threadIdx.x;
    const int lane = tid & 31, wid = tid >> 5;
    const int g = lane >> 2, tg = lane & 3;
    const int wm = (wid & 1) * 32;
    const int wn = (wid >> 1) * 24;
    const int row0 = blockIdx.x * 64;
    const int kbase = blockIdx.y * (D_ / KSPLIT);   // 256-wide k slice

    float acc[2][3][4];
#pragma unroll
    for (int i = 0; i < 2; i++)
#pragma unroll
        for (int j = 0; j < 3; j++)
#pragma unroll
            for (int q = 0; q < 4; q++) acc[i][j][q] = 0.f;

    const float* Ab = A + (size_t)row0 * D_;

    auto loadStage = [&](int st, int k0) {
        float* Ad = Asm + st * AST;
#pragma unroll
        for (int i = tid; i < 512; i += 256) {
            int r = i >> 3, c = i & 7;
            cp16(smem_u32(Ad + r * 40 + c * 4), Ab + (size_t)r * D_ + k0 + c * 4);
        }
        float* Bd = Bsm + st * BST;
#pragma unroll
        for (int i = tid; i < 768; i += 256) {
            int r = i >> 3, c = i & 7;
            cp16(smem_u32(Bd + r * 40 + c * 4), Bw + (size_t)r * D_ + k0 + c * 4);
        }
        CP_COMMIT();
    };
    auto compute = [&](int st) {
        const float* Ad = Asm + st * AST;
        const float* Bd = Bsm + st * BST;
#pragma unroll
        for (int ks = 0; ks < 4; ks++) {
            const int kk = ks * 8 + 2 * tg;
            uint32_t a[2][4];
#pragma unroll
            for (int i = 0; i < 2; i++) {
                const float* ap = Ad + (wm + i * 16 + g) * 40 + kk;
                uint2 v0 = *(const uint2*)ap;
                uint2 v1 = *(const uint2*)(ap + 8 * 40);
                a[i][0] = v0.x; a[i][2] = v0.y;
                a[i][1] = v1.x; a[i][3] = v1.y;
            }
#pragma unroll
            for (int j = 0; j < 3; j++) {
                const float* bp = Bd + (wn + j * 8 + g) * 40 + kk;
                uint2 vb = *(const uint2*)bp;
                uint32_t b[2] = { vb.x, vb.y };
                mma8(acc[0][j], a[0], b);
                mma8(acc[1][j], a[1], b);
            }
        }
    };

    loadStage(0, kbase);
    int st = 0;
    for (int kk = 0; kk < D_ / KSPLIT; kk += 32) {
        asm volatile("cp.async.wait_group 0;" ::: "memory");
        __syncthreads();
        if (kk + 32 < D_ / KSPLIT) loadStage(st ^ 1, kbase + kk + 32);
        compute(st);
        st ^= 1;
    }

    float* P = g_part + (size_t)blockIdx.y * MPAD * NHEAD;
#pragma unroll
    for (int i = 0; i < 2; i++) {
#pragma unroll
        for (int j = 0; j < 3; j++) {
            int c = wn + j * 8 + tg * 2;
#pragma unroll
            for (int rr = 0; rr < 2; rr++) {
                int row = row0 + wm + i * 16 + g + rr * 8;
                float2 v;
                v.x = acc[i][j][rr * 2 + 0];
                v.y = acc[i][j][rr * 2 + 1];
                *(float2*)(P + (size_t)row * NHEAD + c) = v;
            }
        }
    }
}

// ===========================================================================
// 6) reduce split-K partials + bias -> wcl / bin (float4 path)
// ===========================================================================
__global__ void reduce_head(float* __restrict__ wcl, float* __restrict__ bin) {
    int i = blockIdx.x * 256 + threadIdx.x;      // 4-col group index
    if (i >= M_ * (NHEAD / 4)) return;
    int r = i / (NHEAD / 4), cg = i - r * (NHEAD / 4);
    int c = cg * 4;
    float4 s = *(const float4*)(g_hb + c);
#pragma unroll
    for (int p = 0; p < KSPLIT; p++) {
        float4 v = *(const float4*)(g_part + (size_t)p * MPAD * NHEAD + (size_t)r * NHEAD + c);
        s.x += v.x; s.y += v.y; s.z += v.z; s.w += v.w;
    }
    if (c < NMUT) *(float4*)(wcl + (size_t)r * NMUT + c) = s;
    else          *(float4*)(bin + (size_t)r * NBIN + (c - NMUT)) = s;
}

// ===========================================================================
extern "C" void kernel_launch(void* const* d_in, const int* in_sizes, int n_in,
                              void* d_out, int out_size)
{
    const float* features = (const float*)d_in[0];
    const int*   wstarts  = (const int*)d_in[1];
    const float* dense_w  = (const float*)d_in[2];
    const float* dense_b  = (const float*)d_in[3];
    const float* out_w    = (const float*)d_in[4];
    const float* out_b    = (const float*)d_in[5];
    const float* bin_w    = (const float*)d_in[6];
    const float* bin_b    = (const float*)d_in[7];
    (void)in_sizes; (void)n_in; (void)out_size;

    float *wf, *h, *wt, *hw;
    cudaGetSymbolAddress((void**)&wf, g_wf);
    cudaGetSymbolAddress((void**)&h,  g_h);
    cudaGetSymbolAddress((void**)&wt, g_wt);
    cudaGetSymbolAddress((void**)&hw, g_hw);

    float* wcl = (float*)d_out;                        // [M, 64]
    float* bin = (float*)d_out + (size_t)M_ * NMUT;    // [M, 32]

    const int SMEM_MAIN = 2 * (128 * 40 + 128 * 40) * 4;   // 81920
    const int SMEM_HEAD = 2 * (64 * 40 + 96 * 40) * 4;     // 51200
    cudaFuncSetAttribute(tc_main, cudaFuncAttributeMaxDynamicSharedMemorySize, SMEM_MAIN);
    cudaFuncSetAttribute(tc_head, cudaFuncAttributeMaxDynamicSharedMemorySize, SMEM_HEAD);

    // one-time side stream + fork/join events (created outside capture)
    static cudaStream_t s_side = nullptr;
    static cudaEvent_t ev_fork = nullptr, ev_w = nullptr, ev_join = nullptr;
    if (s_side == nullptr) {
        cudaStreamCreateWithFlags(&s_side, cudaStreamNonBlocking);
        cudaEventCreateWithFlags(&ev_fork, cudaEventDisableTiming);
        cudaEventCreateWithFlags(&ev_w,    cudaEventDisableTiming);
        cudaEventCreateWithFlags(&ev_join, cudaEventDisableTiming);
    }

    cudaEventRecord(ev_fork, 0);
    // main: scan(1), wf(2)
    scan_kernel<<<B_, 256>>>(wstarts);
    wf_kernel<<<M_, 256>>>(features);
    // side: roundw(3) — concurrent with scan+wf
    cudaStreamWaitEvent(s_side, ev_fork, 0);
    roundw_kernel<<<D_ * D_ / 4 / 256, 256, 0, s_side>>>(dense_w);
    cudaEventRecord(ev_w, s_side);
    // main: tc_main(4) — needs wf (stream order) + roundw (event)
    cudaStreamWaitEvent(0, ev_w, 0);
    tc_main<<<dim3(8, MPAD / 128), 256, SMEM_MAIN>>>(wf, wt, dense_b, h);
    // side: head-weight prep (5,6) — concurrent with tc_main
    headw_copy<<<NMUT * D_ / 4 / 256, 256, 0, s_side>>>(out_w, out_b);
    headw_bin<<<dim3(16, 4), 256, 0, s_side>>>(out_w, out_b, bin_w, bin_b);
    cudaEventRecord(ev_join, s_side);
    // join, then heads
    cudaStreamWaitEvent(0, ev_join, 0);
    tc_head<<<dim3(MPAD / 64, KSPLIT), 256, SMEM_HEAD>>>(h, hw);
    reduce_head<<<(M_ * (NHEAD / 4) + 255) / 256, 256>>>(wcl, bin);
}

// round 16
// speedup vs baseline: 1.7394x; 1.7259x over previous
#include <cuda_runtime.h>
#include <cuda_fp16.h>
#include <cstdint>

#define B_    16
#define T_    2048
#define D_    1024
#define DW    (D_ / 2)            // 512 uint32 words (fp16 pairs) per row
#define TT_   2046
#define MW_   682
#define M_    (B_ * MW_)          // 10912
#define MPAD  11008               // 86 * 128 = 172 * 64
#define NMUT  64
#define NBIN  32
#define NHEAD 96                  // 64 class + 32 binary (fused)
#define KSPLIT 4

// fp16 GEMM operands. Each 8-pair (16 k) group is stored pair-permuted:
// pair p -> position 2*(p&3)|(p>>2), so an mma thread's two k16-frag pairs
// (tg, tg+4) are adjacent -> one LDS.64 per fragment.
__device__ __half g_wf[MPAD * D_];       // word features
__device__ __half g_h [MPAD * D_];       // tanh hidden
__device__ __half g_wt[D_ * D_];         // dense_w
__device__ __half g_hw[NHEAD * D_];      // fused head weights
__device__ float  g_hb[NHEAD];           // fused head bias (fp32)
__device__ float  g_part[KSPLIT * MPAD * NHEAD];  // head split-K partials
__device__ int    g_begin[M_];
__device__ int    g_cnt  [M_];

// ===========================================================================
// helpers
// ===========================================================================
__device__ __forceinline__ uint32_t smem_u32(const void* p) {
    return (uint32_t)__cvta_generic_to_shared(p);
}
__device__ __forceinline__ void cp16(uint32_t dst, const void* src) {
    asm volatile("cp.async.cg.shared.global [%0], [%1], 16;\n" :: "r"(dst), "l"(src));
}
#define CP_COMMIT() asm volatile("cp.async.commit_group;" ::: "memory")

__device__ __forceinline__ float tanh_fast(float x) {
    float y;
    asm("tanh.approx.f32 %0, %1;" : "=f"(y) : "f"(x));
    return y;
}
__device__ __forceinline__ int pperm(int l) {        // pair perm within 8
    return ((l & 3) << 1) | (l >> 2);
}
__device__ __forceinline__ int ppos(int pr) {        // global pair position
    return (pr & ~7) | pperm(pr & 7);
}
// fp16 m16n8k16, fp32 accumulate
__device__ __forceinline__ void mma16(float* c, const uint32_t* a, const uint32_t* b) {
    asm volatile("mma.sync.aligned.m16n8k16.row.col.f32.f16.f16.f32 "
        "{%0,%1,%2,%3}, {%4,%5,%6,%7}, {%8,%9}, {%0,%1,%2,%3};"
        : "+f"(c[0]), "+f"(c[1]), "+f"(c[2]), "+f"(c[3])
        : "r"(a[0]), "r"(a[1]), "r"(a[2]), "r"(a[3]), "r"(b[0]), "r"(b[1]));
}

// ===========================================================================
// 1) per-batch scan of word_starts -> word begin token + token count
// ===========================================================================
__global__ void scan_kernel(const int* __restrict__ ws) {
    int b = blockIdx.x;
    const int* w = ws + b * TT_;
    __shared__ int partial[256];
    __shared__ int scnt[MW_];
    int tid = threadIdx.x;
    for (int i = tid; i < MW_; i += 256) scnt[i] = 0;

    int vals[8];
    int s = 0;
#pragma unroll
    for (int i = 0; i < 8; i++) {
        int t = tid * 8 + i;
        int v = (t < TT_) ? w[t] : 0;
        vals[i] = v; s += v;
    }
    partial[tid] = s;
    __syncthreads();
    for (int off = 1; off < 256; off <<= 1) {
        int v = partial[tid];
        int add = (tid >= off) ? partial[tid - off] : 0;
        __syncthreads();
        partial[tid] = v + add;
        __syncthreads();
    }
    int run = (tid > 0) ? partial[tid - 1] : 0;
#pragma unroll
    for (int i = 0; i < 8; i++) {
        int t = tid * 8 + i;
        if (t < TT_) {
            run += vals[i];
            int seg = run - 1;
            if (seg >= 0 && seg < MW_) {
                if (vals[i]) g_begin[b * MW_ + seg] = t;
                atomicAdd(&scnt[seg], 1);
            }
        }
    }
    __syncthreads();
    for (int i = tid; i < MW_; i += 256) g_cnt[b * MW_ + i] = scnt[i];
}

// ===========================================================================
// 2) word-feature segment sums -> fp16, pair-permuted
// ===========================================================================
__global__ void wf_kernel(const float* __restrict__ feat) {
    int m = blockIdx.x;
    int b = m / MW_;
    int tid = threadIdx.x;                       // float4 index 0..255
    int cnt = g_cnt[m];
    __half2* row = (__half2*)(g_wf + (size_t)m * D_);
    int pos0 = ppos(2 * tid), pos1 = ppos(2 * tid + 1);
    if (cnt == 0) {
        __half2 one = __float22half2_rn(make_float2(1.f, 1.f));
        row[pos0] = one; row[pos1] = one;
        return;
    }
    int t0 = g_begin[m];
    const float4* base = (const float4*)(feat + ((size_t)b * T_ + 1 + t0) * D_);
    float4 acc = base[tid];
    for (int i = 1; i < cnt; i++) {
        float4 v = base[(size_t)i * (D_ / 4) + tid];
        acc.x += v.x; acc.y += v.y; acc.z += v.z; acc.w += v.w;
    }
    row[pos0] = __float22half2_rn(make_float2(acc.x, acc.y));
    row[pos1] = __float22half2_rn(make_float2(acc.z, acc.w));
}

// ===========================================================================
// 2b) dense_w -> fp16, pair-permuted
// ===========================================================================
__global__ void roundw_kernel(const float* __restrict__ src) {
    int i = blockIdx.x * 256 + threadIdx.x;      // float4 index over D*D/4
    float4 v = ((const float4*)src)[i];
    int base8 = (2 * i) & ~7;                    // pair-group base of pair 2i
    __half2* dst = (__half2*)g_wt;
    dst[(2 * i & ~7) | pperm(2 * i & 7)] = __float22half2_rn(make_float2(v.x, v.y));
    dst[((2 * i + 1) & ~7) | pperm((2 * i + 1) & 7)] = __float22half2_rn(make_float2(v.z, v.w));
    (void)base8;
}

// ===========================================================================
// 3a) g_hw rows 0..63 = fp16(out_w) pair-permuted; g_hb[0..63] = out_b
// ===========================================================================
__global__ void headw_copy(const float* __restrict__ out_w, const float* __restrict__ out_b) {
    int i = blockIdx.x * 256 + threadIdx.x;      // float4 index over 64*1024/4
    float4 v = ((const float4*)out_w)[i];
    __half2* dst = (__half2*)g_hw;
    dst[(2 * i & ~7) | pperm(2 * i & 7)] = __float22half2_rn(make_float2(v.x, v.y));
    dst[((2 * i + 1) & ~7) | pperm((2 * i + 1) & 7)] = __float22half2_rn(make_float2(v.z, v.w));
    if (blockIdx.x == 0 && threadIdx.x < NMUT) g_hb[threadIdx.x] = out_b[threadIdx.x];
}

// ===========================================================================
// 3b) g_hw rows 64..95 = fp16(bin_w[:,64:] + bin_w[:,:64] @ out_w), permuted
//     grid (16, 4): block = 32 col-pairs x 8 rows
// ===========================================================================
__global__ void headw_bin(const float* __restrict__ out_w, const float* __restrict__ out_b,
                          const float* __restrict__ bin_w, const float* __restrict__ bin_b) {
    __shared__ float w1[8][NMUT];
    int tid = threadIdx.x;
    int rb  = blockIdx.y * 8;
    for (int i = tid; i < 8 * NMUT; i += 256) {
        int r = i >> 6, j = i & 63;
        w1[r][j] = bin_w[(size_t)(rb + r) * (D_ + NMUT) + j];
    }
    __syncthreads();

    int p  = tid & 31;                           // pair within block
    int r  = tid >> 5;                           // local row 0..7
    int pr = blockIdx.x * 32 + p;                // global pair 0..511
    int col = pr * 2;
    float a0 = bin_w[(size_t)(rb + r) * (D_ + NMUT) + NMUT + col];
    float a1 = bin_w[(size_t)(rb + r) * (D_ + NMUT) + NMUT + col + 1];
#pragma unroll 8
    for (int j = 0; j < NMUT; j++) {
        float2 v = *(const float2*)(out_w + (size_t)j * D_ + col);
        a0 += w1[r][j] * v.x;
        a1 += w1[r][j] * v.y;
    }
    __half2* dst = (__half2*)(g_hw + (size_t)(NMUT + rb + r) * D_);
    dst[ppos(pr)] = __float22half2_rn(make_float2(a0, a1));

    if (blockIdx.x == 0 && blockIdx.y == 0 && tid < NBIN) {
        float bb = bin_b[tid];
        for (int j = 0; j < NMUT; j++)
            bb += bin_w[(size_t)tid * (D_ + NMUT) + j] * out_b[j];
        g_hb[NMUT + tid] = bb;
    }
}

// ===========================================================================
// 4) main fp16 GEMM: h = tanh(wf @ wt^T + b).  128x128 CTA tile, BK=64,
//    m16n8k16, 2-stage cp.async, 256 thr, 8 warps (4m x 2n), 32x64 warp tile.
//    Half the HMMA count / crossbar bytes / barriers of the tf32 version.
// ===========================================================================
__global__ __launch_bounds__(256) void tc_main(
    const __half* __restrict__ A, const __half* __restrict__ Bw,
    const float* __restrict__ bias, __half* __restrict__ O1)
{
    constexpr int AST = 128 * 40;                // words per stage
    constexpr int BST = 128 * 40;
    extern __shared__ uint32_t smem[];
    uint32_t* Asm = smem;                        // [2][128][40] words
    uint32_t* Bsm = smem + 2 * AST;

    const int tid = threadIdx.x;
    const int lane = tid & 31, wid = tid >> 5;
    const int g = lane >> 2, tg = lane & 3;
    const int wm = (wid & 3) * 32;
    const int wn = (wid >> 2) * 64;
    const int row0 = blockIdx.y * 128;
    const int col0 = blockIdx.x * 128;

    float acc[2][8][4];
#pragma unroll
    for (int i = 0; i < 2; i++)
#pragma unroll
        for (int j = 0; j < 8; j++)
#pragma unroll
            for (int q = 0; q < 4; q++) acc[i][j][q] = 0.f;

    const uint32_t* Ag = (const uint32_t*)A + (size_t)row0 * DW;
    const uint32_t* Bg = (const uint32_t*)Bw + (size_t)col0 * DW;

    auto loadStage = [&](int st, int kw0) {      // kw0 = word offset
        uint32_t* Ad = Asm + st * AST;
#pragma unroll
        for (int i = tid; i < 1024; i += 256) {
            int r = i >> 3, c = (i & 7) * 4;
            cp16(smem_u32(Ad + r * 40 + c), Ag + (size_t)r * DW + kw0 + c);
        }
        uint32_t* Bd = Bsm + st * BST;
#pragma unroll
        for (int i = tid; i < 1024; i += 256) {
            int r = i >> 3, c = (i & 7) * 4;
            cp16(smem_u32(Bd + r * 40 + c), Bg + (size_t)r * DW + kw0 + c);
        }
        CP_COMMIT();
    };
    auto compute = [&](int st) {
        const uint32_t* Ad = Asm + st * AST;
        const uint32_t* Bd = Bsm + st * BST;
#pragma unroll
        for (int ks = 0; ks < 4; ks++) {         // 4 x k16 per 64-k chunk
            const int kk = ks * 8 + 2 * tg;
            uint32_t a[2][4];
#pragma unroll
            for (int i = 0; i < 2; i++) {
                const uint32_t* ap = Ad + (wm + i * 16 + g) * 40 + kk;
                uint2 v0 = *(const uint2*)ap;            // pairs tg, tg+4
                uint2 v1 = *(const uint2*)(ap + 8 * 40);
                a[i][0] = v0.x; a[i][2] = v0.y;
                a[i][1] = v1.x; a[i][3] = v1.y;
            }
#pragma unroll
            for (int j = 0; j < 8; j++) {
                const uint32_t* bp = Bd + (wn + j * 8 + g) * 40 + kk;
                uint2 vb = *(const uint2*)bp;
                uint32_t b[2] = { vb.x, vb.y };
                mma16(acc[0][j], a[0], b);
                mma16(acc[1][j], a[1], b);
            }
        }
    };

    loadStage(0, 0);
    int st = 0;
    for (int kw = 0; kw < DW; kw += 32) {        // 16 chunks of 64 k
        asm volatile("cp.async.wait_group 0;" ::: "memory");
        __syncthreads();
        if (kw + 32 < DW) loadStage(st ^ 1, kw + 32);
        compute(st);
        st ^= 1;
    }

    // epilogue: bias + tanh.approx -> fp16 pair-permuted stores
#pragma unroll
    for (int i = 0; i < 2; i++) {
#pragma unroll
        for (int j = 0; j < 8; j++) {
            int r = row0 + wm + i * 16 + g;
            int c = col0 + wn + j * 8 + tg * 2;
            int pos = ppos(c >> 1);
            __half2 x01 = __float22half2_rn(make_float2(
                tanh_fast(acc[i][j][0] + bias[c]),
                tanh_fast(acc[i][j][1] + bias[c + 1])));
            __half2 x23 = __float22half2_rn(make_float2(
                tanh_fast(acc[i][j][2] + bias[c]),
                tanh_fast(acc[i][j][3] + bias[c + 1])));
            ((__half2*)(O1 + (size_t)r * D_))[pos] = x01;
            ((__half2*)(O1 + (size_t)(r + 8) * D_))[pos] = x23;
        }
    }
}

// ===========================================================================
// 5) head GEMM split-K (fp16): partial[s] = h @ g_hw^T over 256-k slice s
//    grid (172, 4); BM=64, BN=96, BK=64 (4 chunks), fp32 partials out.
// ===========================================================================
__global__ __launch_bounds__(256) void tc_head(
    const __half* __restrict__ A, const __half* __restrict__ Bw)
{
    constexpr int AST = 64 * 40;
    constexpr int BST = 96 * 40;
    extern __shared__ uint32_t smem[];
    uint32_t* Asm = smem;                        // [2][64][40] words
    uint32_t* Bsm = smem + 2 * AST;              // [2][96][40] words

    const int tid = threadIdx.x;
    const int lane = tid & 31, wid = tid >> 5;
    const int g = lane >> 2, tg = lane & 3;
    const int wm = (wid & 1) * 32;
    const int wn = (wid >> 1) * 24;
    const int row0 = blockIdx.x * 64;
    const int kwbase = blockIdx.y * (DW / KSPLIT);   // 128-word k slice

    float acc[2][3][4];
#pragma unroll
    for (int i = 0; i < 2; i++)
#pragma unroll
        for (int j = 0; j < 3; j++)
#pragma unroll
            for (int q = 0; q < 4; q++) acc[i][j][q] = 0.f;

    const uint32_t* Ag = (const uint32_t*)A + (size_t)row0 * DW;
    const uint32_t* Bg = (const uint32_t*)Bw;

    auto loadStage = [&](int st, int kw0) {
        uint32_t* Ad = Asm + st * AST;
#pragma unroll
        for (int i = tid; i < 512; i += 256) {
            int r = i >> 3, c = (i & 7) * 4;
            cp16(smem_u32(Ad + r * 40 + c), Ag + (size_t)r * DW + kw0 + c);
        }
        uint32_t* Bd = Bsm + st * BST;
#pragma unroll
        for (int i = tid; i < 768; i += 256) {
            int r = i >> 3, c = (i & 7) * 4;
            cp16(smem_u32(Bd + r * 40 + c), Bg + (size_t)r * DW + kw0 + c);
        }
        CP_COMMIT();
    };
    auto compute = [&](int st) {
        const uint32_t* Ad = Asm + st * AST;
        const uint32_t* Bd = Bsm + st * BST;
#pragma unroll
        for (int ks = 0; ks < 4; ks++) {
            const int kk = ks * 8 + 2 * tg;
            uint32_t a[2][4];
#pragma unroll
            for (int i = 0; i < 2; i++) {
                const uint32_t* ap = Ad + (wm + i * 16 + g) * 40 + kk;
                uint2 v0 = *(const uint2*)ap;
                uint2 v1 = *(const uint2*)(ap + 8 * 40);
                a[i][0] = v0.x; a[i][2] = v0.y;
                a[i][1] = v1.x; a[i][3] = v1.y;
            }
#pragma unroll
            for (int j = 0; j < 3; j++) {
                const uint32_t* bp = Bd + (wn + j * 8 + g) * 40 + kk;
                uint2 vb = *(const uint2*)bp;
                uint32_t b[2] = { vb.x, vb.y };
                mma16(acc[0][j], a[0], b);
                mma16(acc[1][j], a[1], b);
            }
        }
    };

    loadStage(0, kwbase);
    int st = 0;
    for (int kw = 0; kw < DW / KSPLIT; kw += 32) {   // 4 chunks
        asm volatile("cp.async.wait_group 0;" ::: "memory");
        __syncthreads();
        if (kw + 32 < DW / KSPLIT) loadStage(st ^ 1, kwbase + kw + 32);
        compute(st);
        st ^= 1;
    }

    float* P = g_part + (size_t)blockIdx.y * MPAD * NHEAD;
#pragma unroll
    for (int i = 0; i < 2; i++) {
#pragma unroll
        for (int j = 0; j < 3; j++) {
            int c = wn + j * 8 + tg * 2;
#pragma unroll
            for (int rr = 0; rr < 2; rr++) {
                int row = row0 + wm + i * 16 + g + rr * 8;
                float2 v;
                v.x = acc[i][j][rr * 2 + 0];
                v.y = acc[i][j][rr * 2 + 1];
                *(float2*)(P + (size_t)row * NHEAD + c) = v;
            }
        }
    }
}

// ===========================================================================
// 6) reduce split-K partials + bias -> wcl / bin (float4 path)
// ===========================================================================
__global__ void reduce_head(float* __restrict__ wcl, float* __restrict__ bin) {
    int i = blockIdx.x * 256 + threadIdx.x;      // 4-col group index
    if (i >= M_ * (NHEAD / 4)) return;
    int r = i / (NHEAD / 4), cg = i - r * (NHEAD / 4);
    int c = cg * 4;
    float4 s = *(const float4*)(g_hb + c);
#pragma unroll
    for (int p = 0; p < KSPLIT; p++) {
        float4 v = *(const float4*)(g_part + (size_t)p * MPAD * NHEAD + (size_t)r * NHEAD + c);
        s.x += v.x; s.y += v.y; s.z += v.z; s.w += v.w;
    }
    if (c < NMUT) *(float4*)(wcl + (size_t)r * NMUT + c) = s;
    else          *(float4*)(bin + (size_t)r * NBIN + (c - NMUT)) = s;
}

// ===========================================================================
extern "C" void kernel_launch(void* const* d_in, const int* in_sizes, int n_in,
                              void* d_out, int out_size)
{
    const float* features = (const float*)d_in[0];
    const int*   wstarts  = (const int*)d_in[1];
    const float* dense_w  = (const float*)d_in[2];
    const float* dense_b  = (const float*)d_in[3];
    const float* out_w    = (const float*)d_in[4];
    const float* out_b    = (const float*)d_in[5];
    const float* bin_w    = (const float*)d_in[6];
    const float* bin_b    = (const float*)d_in[7];
    (void)in_sizes; (void)n_in; (void)out_size;

    __half *wf, *h, *wt, *hw;
    cudaGetSymbolAddress((void**)&wf, g_wf);
    cudaGetSymbolAddress((void**)&h,  g_h);
    cudaGetSymbolAddress((void**)&wt, g_wt);
    cudaGetSymbolAddress((void**)&hw, g_hw);

    float* wcl = (float*)d_out;                        // [M, 64]
    float* bin = (float*)d_out + (size_t)M_ * NMUT;    // [M, 32]

    const int SMEM_MAIN = 2 * (128 * 40 + 128 * 40) * 4;   // 81920 B
    const int SMEM_HEAD = 2 * (64 * 40 + 96 * 40) * 4;     // 51200 B
    cudaFuncSetAttribute(tc_main, cudaFuncAttributeMaxDynamicSharedMemorySize, SMEM_MAIN);
    cudaFuncSetAttribute(tc_head, cudaFuncAttributeMaxDynamicSharedMemorySize, SMEM_HEAD);

    // one-time side stream + fork/join events (created outside capture)
    static cudaStream_t s_side = nullptr;
    static cudaEvent_t ev_fork = nullptr, ev_w = nullptr, ev_join = nullptr;
    if (s_side == nullptr) {
        cudaStreamCreateWithFlags(&s_side, cudaStreamNonBlocking);
        cudaEventCreateWithFlags(&ev_fork, cudaEventDisableTiming);
        cudaEventCreateWithFlags(&ev_w,    cudaEventDisableTiming);
        cudaEventCreateWithFlags(&ev_join, cudaEventDisableTiming);
    }

    cudaEventRecord(ev_fork, 0);
    // main: scan(1), wf(2)
    scan_kernel<<<B_, 256>>>(wstarts);
    wf_kernel<<<M_, 256>>>(features);
    // side: roundw — concurrent with scan+wf
    cudaStreamWaitEvent(s_side, ev_fork, 0);
    roundw_kernel<<<D_ * D_ / 4 / 256, 256, 0, s_side>>>(dense_w);
    cudaEventRecord(ev_w, s_side);
    // main: tc_main — needs wf (stream order) + roundw (event)
    cudaStreamWaitEvent(0, ev_w, 0);
    tc_main<<<dim3(8, MPAD / 128), 256, SMEM_MAIN>>>(wf, wt, dense_b, h);
    // side: head-weight prep — concurrent with tc_main
    headw_copy<<<NMUT * D_ / 4 / 256, 256, 0, s_side>>>(out_w, out_b);
    headw_bin<<<dim3(16, 4), 256, 0, s_side>>>(out_w, out_b, bin_w, bin_b);
    cudaEventRecord(ev_join, s_side);
    // join, then heads
    cudaStreamWaitEvent(0, ev_join, 0);
    tc_head<<<dim3(MPAD / 64, KSPLIT), 256, SMEM_HEAD>>>(h, hw);
    reduce_head<<<(M_ * (NHEAD / 4) + 255) / 256, 256>>>(wcl, bin);
}